// round 1
// baseline (speedup 1.0000x reference)
#include <cuda_runtime.h>
#include <math.h>

// ---------------------------------------------------------------------------
// TransformerBlock baseline (fp32 SIMT)
//   x1  = x + proj( attn( LN1(x) ) )
//   out = x1 + W2( gelu( W1( LN2(x1) ) + b1 ) ) + b2
// Shapes: B=4, T=2048 (BT=8192), C=1024, H=16, D=64, DFF=4096
// ---------------------------------------------------------------------------

#define BT   8192
#define C    1024
#define C3   3072
#define H    16
#define D    64
#define DFF  4096
#define T    2048
#define EPS  1e-5f

// Scratch (allocation-free rule: __device__ globals)
__device__ float g_ln[BT * C];        // LN1 / LN2 output (reused)
__device__ float g_qkv[BT * C3];      // QKV projection
__device__ float g_attn[BT * C];      // attention output (heads merged)
__device__ float g_h1[BT * DFF];      // FFN hidden

// ---------------------------------------------------------------------------
// LayerNorm: one block per row (1024 elems), 256 threads, float4 I/O
// ---------------------------------------------------------------------------
__global__ __launch_bounds__(256) void ln_kernel(
    const float* __restrict__ x, const float* __restrict__ g,
    const float* __restrict__ beta, float* __restrict__ out)
{
    int row = blockIdx.x;
    int t = threadIdx.x;
    const float* xr = x + (size_t)row * C;
    float4 xv = *(const float4*)(xr + t * 4);
    float s  = xv.x + xv.y + xv.z + xv.w;
    float s2 = xv.x * xv.x + xv.y * xv.y + xv.z * xv.z + xv.w * xv.w;

    #pragma unroll
    for (int o = 16; o > 0; o >>= 1) {
        s  += __shfl_xor_sync(0xffffffffu, s,  o);
        s2 += __shfl_xor_sync(0xffffffffu, s2, o);
    }
    __shared__ float ss[8], ss2[8];
    int w = t >> 5, lane = t & 31;
    if (lane == 0) { ss[w] = s; ss2[w] = s2; }
    __syncthreads();
    if (w == 0) {
        s  = (lane < 8) ? ss[lane]  : 0.f;
        s2 = (lane < 8) ? ss2[lane] : 0.f;
        #pragma unroll
        for (int o = 4; o > 0; o >>= 1) {
            s  += __shfl_xor_sync(0xffffffffu, s,  o);
            s2 += __shfl_xor_sync(0xffffffffu, s2, o);
        }
        if (lane == 0) { ss[0] = s; ss2[0] = s2; }
    }
    __syncthreads();
    float mu  = ss[0] * (1.0f / C);
    float var = ss2[0] * (1.0f / C) - mu * mu;
    float inv = rsqrtf(var + EPS);

    float4 gv = *(const float4*)(g + t * 4);
    float4 bv = *(const float4*)(beta + t * 4);
    float4 ov;
    ov.x = (xv.x - mu) * inv * gv.x + bv.x;
    ov.y = (xv.y - mu) * inv * gv.y + bv.y;
    ov.z = (xv.z - mu) * inv * gv.z + bv.z;
    ov.w = (xv.w - mu) * inv * gv.w + bv.w;
    *(float4*)(out + (size_t)row * C + t * 4) = ov;
}

// ---------------------------------------------------------------------------
// SGEMM 128x128x8, 256 threads, 8x8 register micro-tile.
// C[M,N] = A[M,K] @ B[K,N] (+bias[n]) (+gelu) (+resid[M,N])
// M%128==0, N%128==0, K%8==0 (true for all call sites)
// ACT: 0 = none, 1 = exact gelu
// ---------------------------------------------------------------------------
__device__ __forceinline__ float gelu_exact(float v) {
    return 0.5f * v * (1.0f + erff(v * 0.70710678118654752f));
}

template<int ACT, bool BIAS, bool RESID>
__global__ __launch_bounds__(256) void gemm_kernel(
    const float* __restrict__ A, const float* __restrict__ B,
    const float* __restrict__ bias, const float* __restrict__ resid,
    float* __restrict__ Cout, int M, int N, int K)
{
    __shared__ float As[8][128];
    __shared__ float Bs[8][128];

    int t  = threadIdx.x;
    int bm = blockIdx.y * 128;
    int bn = blockIdx.x * 128;

    int a_m  = t >> 1;           // 0..127
    int a_k4 = (t & 1) * 4;      // 0 or 4
    int b_k  = t >> 5;           // 0..7
    int b_n4 = (t & 31) * 4;     // 0..124

    const float* Aptr = A + (size_t)(bm + a_m) * K + a_k4;
    const float* Bptr = B + (size_t)b_k * N + bn + b_n4;

    int tx = t & 15, ty = t >> 4;
    float acc[8][8];
    #pragma unroll
    for (int i = 0; i < 8; i++)
        #pragma unroll
        for (int j = 0; j < 8; j++) acc[i][j] = 0.f;

    for (int k0 = 0; k0 < K; k0 += 8) {
        float4 av = *(const float4*)Aptr;  Aptr += 8;
        float4 bv = *(const float4*)Bptr;  Bptr += (size_t)8 * N;
        As[a_k4 + 0][a_m] = av.x;
        As[a_k4 + 1][a_m] = av.y;
        As[a_k4 + 2][a_m] = av.z;
        As[a_k4 + 3][a_m] = av.w;
        *(float4*)&Bs[b_k][b_n4] = bv;
        __syncthreads();

        #pragma unroll
        for (int kk = 0; kk < 8; kk++) {
            float ar[8], br[8];
            *(float4*)(ar)     = *(const float4*)&As[kk][ty * 8];
            *(float4*)(ar + 4) = *(const float4*)&As[kk][ty * 8 + 4];
            *(float4*)(br)     = *(const float4*)&Bs[kk][tx * 8];
            *(float4*)(br + 4) = *(const float4*)&Bs[kk][tx * 8 + 4];
            #pragma unroll
            for (int i = 0; i < 8; i++)
                #pragma unroll
                for (int j = 0; j < 8; j++)
                    acc[i][j] += ar[i] * br[j];
        }
        __syncthreads();
    }

    #pragma unroll
    for (int i = 0; i < 8; i++) {
        int m = bm + ty * 8 + i;
        #pragma unroll
        for (int j = 0; j < 8; j += 4) {
            int n = bn + tx * 8 + j;
            float4 v = make_float4(acc[i][j], acc[i][j+1], acc[i][j+2], acc[i][j+3]);
            if (BIAS) {
                float4 bb = *(const float4*)(bias + n);
                v.x += bb.x; v.y += bb.y; v.z += bb.z; v.w += bb.w;
            }
            if (ACT == 1) {
                v.x = gelu_exact(v.x); v.y = gelu_exact(v.y);
                v.z = gelu_exact(v.z); v.w = gelu_exact(v.w);
            }
            if (RESID) {
                float4 rr = *(const float4*)(resid + (size_t)m * N + n);
                v.x += rr.x; v.y += rr.y; v.z += rr.z; v.w += rr.w;
            }
            *(float4*)(Cout + (size_t)m * N + n) = v;
        }
    }
}

// ---------------------------------------------------------------------------
// Attention: full softmax over T=2048 keys, no mask.
// Grid (T/128, H, B); 128 threads, 1 thread = 1 query row.
// q (pre-scaled) + acc in registers; 32-key K/V tiles in smem (broadcast reads).
// qkv layout: [token][3C] with q@0, k@C, v@2C; head h occupies cols h*64..h*64+63.
// ---------------------------------------------------------------------------
__global__ __launch_bounds__(128) void attn_kernel(
    const float* __restrict__ qkv, float* __restrict__ out)
{
    int qt = blockIdx.x;
    int h  = blockIdx.y;
    int b  = blockIdx.z;
    int t  = threadIdx.x;
    int q_token = b * T + qt * 128 + t;

    const float* qptr = qkv + (size_t)q_token * C3 + h * D;
    float q[D];
    #pragma unroll
    for (int d = 0; d < D; d += 4) {
        float4 v = *(const float4*)(qptr + d);
        q[d]   = v.x * 0.125f;  // 1/sqrt(64)
        q[d+1] = v.y * 0.125f;
        q[d+2] = v.z * 0.125f;
        q[d+3] = v.w * 0.125f;
    }

    float m = -1e30f, l = 0.f;
    float acc[D];
    #pragma unroll
    for (int d = 0; d < D; d++) acc[d] = 0.f;

    __shared__ float Ksh[32][D];
    __shared__ float Vsh[32][D];

    for (int kt = 0; kt < T; kt += 32) {
        // cooperative load: 32 rows x 64 dims as float4 (512 float4 per array)
        #pragma unroll
        for (int i = t; i < 512; i += 128) {
            int r  = i >> 4;
            int d4 = (i & 15) << 2;
            int tok = b * T + kt + r;
            const float* kp = qkv + (size_t)tok * C3 + C + h * D + d4;
            *(float4*)&Ksh[r][d4] = *(const float4*)kp;
            *(float4*)&Vsh[r][d4] = *(const float4*)(kp + C);
        }
        __syncthreads();

        float s[32];
        #pragma unroll
        for (int k = 0; k < 32; k++) {
            float sv = 0.f;
            #pragma unroll
            for (int d = 0; d < D; d += 4) {
                float4 kv = *(const float4*)&Ksh[k][d];
                sv += q[d] * kv.x + q[d+1] * kv.y + q[d+2] * kv.z + q[d+3] * kv.w;
            }
            s[k] = sv;
        }

        float mt = m;
        #pragma unroll
        for (int k = 0; k < 32; k++) mt = fmaxf(mt, s[k]);
        float corr = __expf(m - mt);
        m = mt;
        l *= corr;
        #pragma unroll
        for (int d = 0; d < D; d++) acc[d] *= corr;

        #pragma unroll
        for (int k = 0; k < 32; k++) {
            float p = __expf(s[k] - m);
            l += p;
            #pragma unroll
            for (int d = 0; d < D; d += 4) {
                float4 vv = *(const float4*)&Vsh[k][d];
                acc[d]   += p * vv.x;
                acc[d+1] += p * vv.y;
                acc[d+2] += p * vv.z;
                acc[d+3] += p * vv.w;
            }
        }
        __syncthreads();
    }

    float inv = 1.0f / l;
    float* op = out + (size_t)q_token * C + h * D;
    #pragma unroll
    for (int d = 0; d < D; d += 4) {
        float4 v = make_float4(acc[d] * inv, acc[d+1] * inv, acc[d+2] * inv, acc[d+3] * inv);
        *(float4*)(op + d) = v;
    }
}

// ---------------------------------------------------------------------------
// Launch
// inputs (metadata order): x, ln1_g, ln1_b, ln2_g, ln2_b, w_qkv, w_proj, w1, b1, w2, b2
// ---------------------------------------------------------------------------
extern "C" void kernel_launch(void* const* d_in, const int* in_sizes, int n_in,
                              void* d_out, int out_size)
{
    const float* x      = (const float*)d_in[0];
    const float* ln1_g  = (const float*)d_in[1];
    const float* ln1_b  = (const float*)d_in[2];
    const float* ln2_g  = (const float*)d_in[3];
    const float* ln2_b  = (const float*)d_in[4];
    const float* w_qkv  = (const float*)d_in[5];
    const float* w_proj = (const float*)d_in[6];
    const float* w1     = (const float*)d_in[7];
    const float* b1     = (const float*)d_in[8];
    const float* w2     = (const float*)d_in[9];
    const float* b2     = (const float*)d_in[10];
    float* out = (float*)d_out;

    float* ln   = nullptr;  cudaGetSymbolAddress((void**)&ln,   g_ln);
    float* qkv  = nullptr;  cudaGetSymbolAddress((void**)&qkv,  g_qkv);
    float* attn = nullptr;  cudaGetSymbolAddress((void**)&attn, g_attn);
    float* h1   = nullptr;  cudaGetSymbolAddress((void**)&h1,   g_h1);

    // 1) LN1(x) -> ln
    ln_kernel<<<BT, 256>>>(x, ln1_g, ln1_b, ln);

    // 2) qkv = ln @ w_qkv          [8192,3072]
    {
        dim3 grid(C3 / 128, BT / 128);
        gemm_kernel<0, false, false><<<grid, 256>>>(ln, w_qkv, nullptr, nullptr, qkv, BT, C3, C);
    }

    // 3) attention -> attn         [8192,1024]
    {
        dim3 grid(T / 128, H, 4);
        attn_kernel<<<grid, 128>>>(qkv, attn);
    }

    // 4) out = x + attn @ w_proj   (x1 residual lives in d_out)
    {
        dim3 grid(C / 128, BT / 128);
        gemm_kernel<0, false, true><<<grid, 256>>>(attn, w_proj, nullptr, x, out, BT, C, C);
    }

    // 5) LN2(out) -> ln
    ln_kernel<<<BT, 256>>>(out, ln2_g, ln2_b, ln);

    // 6) h1 = gelu(ln @ w1 + b1)   [8192,4096]
    {
        dim3 grid(DFF / 128, BT / 128);
        gemm_kernel<1, true, false><<<grid, 256>>>(ln, w1, b1, nullptr, h1, BT, DFF, C);
    }

    // 7) out = out + h1 @ w2 + b2
    {
        dim3 grid(C / 128, BT / 128);
        gemm_kernel<0, true, true><<<grid, 256>>>(h1, w2, b2, out, out, BT, C, DFF);
    }
}

// round 3
// speedup vs baseline: 1.7294x; 1.7294x over previous
#include <cuda_runtime.h>
#include <math.h>
#include <stdint.h>

// ---------------------------------------------------------------------------
// TransformerBlock: mma.sync tf32 GEMMs (compute_103-safe) + fp32 attention/LN
// Shapes: B=4, T=2048 (BT=8192), C=1024, H=16, D=64, DFF=4096
// ---------------------------------------------------------------------------

#define BT   8192
#define C    1024
#define C3   3072
#define H    16
#define D    64
#define DFF  4096
#define T    2048
#define EPS  1e-5f

// Scratch (__device__ globals; no allocations allowed)
__device__ float g_ln[BT * C];
__device__ float g_qkv[BT * C3];
__device__ float g_attn[BT * C];
__device__ float g_h1[BT * DFF];

// ---------------------------------------------------------------------------
// Helpers
// ---------------------------------------------------------------------------
__device__ __forceinline__ uint32_t smem_u32(const void* p) {
    uint32_t a;
    asm("{ .reg .u64 t; cvta.to.shared.u64 t, %1; cvt.u32.u64 %0, t; }" : "=r"(a) : "l"(p));
    return a;
}
__device__ __forceinline__ void cp_async16(uint32_t dst, const void* src) {
    asm volatile("cp.async.ca.shared.global [%0], [%1], 16;" :: "r"(dst), "l"(src) : "memory");
}
__device__ __forceinline__ void cp_commit() {
    asm volatile("cp.async.commit_group;" ::: "memory");
}
template<int N>
__device__ __forceinline__ void cp_wait() {
    asm volatile("cp.async.wait_group %0;" :: "n"(N) : "memory");
}
__device__ __forceinline__ uint32_t cvt_tf32(float x) {
    uint32_t u;
    asm("cvt.rna.tf32.f32 %0, %1;" : "=r"(u) : "f"(x));
    return u;
}
__device__ __forceinline__ void mma_16n8k8(float* d, const uint32_t* a, const uint32_t* b) {
    asm volatile(
        "mma.sync.aligned.m16n8k8.row.col.f32.tf32.tf32.f32 "
        "{%0,%1,%2,%3}, {%4,%5,%6,%7}, {%8,%9}, {%0,%1,%2,%3};"
        : "+f"(d[0]), "+f"(d[1]), "+f"(d[2]), "+f"(d[3])
        : "r"(a[0]), "r"(a[1]), "r"(a[2]), "r"(a[3]), "r"(b[0]), "r"(b[1]));
}
__device__ __forceinline__ float gelu_exact(float v) {
    return 0.5f * v * (1.0f + erff(v * 0.70710678118654752f));
}

// ---------------------------------------------------------------------------
// LayerNorm
// ---------------------------------------------------------------------------
__global__ __launch_bounds__(256) void ln_kernel(
    const float* __restrict__ x, const float* __restrict__ g,
    const float* __restrict__ beta, float* __restrict__ out)
{
    int row = blockIdx.x;
    int t = threadIdx.x;
    const float* xr = x + (size_t)row * C;
    float4 xv = *(const float4*)(xr + t * 4);
    float s  = xv.x + xv.y + xv.z + xv.w;
    float s2 = xv.x * xv.x + xv.y * xv.y + xv.z * xv.z + xv.w * xv.w;
    #pragma unroll
    for (int o = 16; o > 0; o >>= 1) {
        s  += __shfl_xor_sync(0xffffffffu, s,  o);
        s2 += __shfl_xor_sync(0xffffffffu, s2, o);
    }
    __shared__ float ss[8], ss2[8];
    int w = t >> 5, lane = t & 31;
    if (lane == 0) { ss[w] = s; ss2[w] = s2; }
    __syncthreads();
    if (w == 0) {
        s  = (lane < 8) ? ss[lane]  : 0.f;
        s2 = (lane < 8) ? ss2[lane] : 0.f;
        #pragma unroll
        for (int o = 4; o > 0; o >>= 1) {
            s  += __shfl_xor_sync(0xffffffffu, s,  o);
            s2 += __shfl_xor_sync(0xffffffffu, s2, o);
        }
        if (lane == 0) { ss[0] = s; ss2[0] = s2; }
    }
    __syncthreads();
    float mu  = ss[0] * (1.0f / C);
    float var = ss2[0] * (1.0f / C) - mu * mu;
    float inv = rsqrtf(var + EPS);
    float4 gv = *(const float4*)(g + t * 4);
    float4 bv = *(const float4*)(beta + t * 4);
    float4 ov;
    ov.x = (xv.x - mu) * inv * gv.x + bv.x;
    ov.y = (xv.y - mu) * inv * gv.y + bv.y;
    ov.z = (xv.z - mu) * inv * gv.z + bv.z;
    ov.w = (xv.w - mu) * inv * gv.w + bv.w;
    *(float4*)(out + (size_t)row * C + t * 4) = ov;
}

// ---------------------------------------------------------------------------
// tf32 mma.sync GEMM: D[M,N] = A[M,K] @ B[K,N] (+bias) (gelu) (+resid)
// CTA tile 128x128, K-chunk 32, double-buffered cp.async.
// 8 warps in 2(m) x 4(n); warp tile 64x32; mma m16n8k8.
// Smem: A chunk [128][36] padded, B chunk [32][132] padded.
// ---------------------------------------------------------------------------
#define A_STRIDE 36
#define B_STRIDE 132
#define ASZ (128 * A_STRIDE)          // floats
#define BSZ (32 * B_STRIDE)           // floats
#define GEMM_SMEM_BYTES (2 * (ASZ + BSZ) * 4)

template<int ACT, bool BIAS, bool RESID>
__global__ __launch_bounds__(256, 2) void gemm_mma(
    const float* __restrict__ A, const float* __restrict__ B,
    const float* __restrict__ bias, const float* __restrict__ resid,
    float* __restrict__ Cout, int M, int N, int K)
{
    extern __shared__ float smem[];
    float* As[2] = { smem,             smem + ASZ };
    float* Bs[2] = { smem + 2 * ASZ,   smem + 2 * ASZ + BSZ };

    int t    = threadIdx.x;
    int lane = t & 31;
    int w    = t >> 5;
    int grp  = lane >> 2;   // 0..7
    int tg   = lane & 3;    // 0..3
    int bm = blockIdx.y * 128;
    int bn = blockIdx.x * 128;
    int wm = (w >> 2) * 64;   // 0 or 64
    int wn = (w & 3) * 32;    // 0,32,64,96

    // staging indices (4 float4 each for A and B per chunk)
    int a_row = t >> 1;            // uses t..t+255 mapping below
    (void)a_row;

    float acc[4][4][4];
    #pragma unroll
    for (int mi = 0; mi < 4; mi++)
        #pragma unroll
        for (int ni = 0; ni < 4; ni++)
            #pragma unroll
            for (int r = 0; r < 4; r++) acc[mi][ni][r] = 0.f;

    const int NCH = K >> 5;

    auto load_chunk = [&](int c) {
        int buf = c & 1;
        uint32_t aBase = smem_u32(As[buf]);
        uint32_t bBase = smem_u32(Bs[buf]);
        int k0 = c << 5;
        // A: 128 rows x 32 cols = 1024 float4 tasks
        #pragma unroll
        for (int it = 0; it < 4; it++) {
            int idx  = t + it * 256;
            int row  = idx >> 3;
            int col4 = (idx & 7) << 2;
            cp_async16(aBase + (uint32_t)(row * A_STRIDE + col4) * 4,
                       A + (size_t)(bm + row) * K + k0 + col4);
        }
        // B: 32 rows x 128 cols = 1024 float4 tasks
        #pragma unroll
        for (int it = 0; it < 4; it++) {
            int idx  = t + it * 256;
            int row  = idx >> 5;
            int col4 = (idx & 31) << 2;
            cp_async16(bBase + (uint32_t)(row * B_STRIDE + col4) * 4,
                       B + (size_t)(k0 + row) * N + bn + col4);
        }
        cp_commit();
    };

    load_chunk(0);

    for (int c = 0; c < NCH; c++) {
        if (c + 1 < NCH) load_chunk(c + 1);
        if (c + 1 < NCH) cp_wait<1>(); else cp_wait<0>();
        __syncthreads();

        int buf = c & 1;
        const float* Asb = As[buf];
        const float* Bsb = Bs[buf];

        #pragma unroll
        for (int ks = 0; ks < 4; ks++) {
            int k = ks << 3;
            uint32_t af[4][4], bf[4][2];
            #pragma unroll
            for (int mi = 0; mi < 4; mi++) {
                const float* ap = Asb + (wm + mi * 16 + grp) * A_STRIDE + k + tg;
                af[mi][0] = cvt_tf32(ap[0]);
                af[mi][1] = cvt_tf32(ap[8 * A_STRIDE]);
                af[mi][2] = cvt_tf32(ap[4]);
                af[mi][3] = cvt_tf32(ap[8 * A_STRIDE + 4]);
            }
            #pragma unroll
            for (int ni = 0; ni < 4; ni++) {
                const float* bp = Bsb + (k + tg) * B_STRIDE + wn + ni * 8 + grp;
                bf[ni][0] = cvt_tf32(bp[0]);
                bf[ni][1] = cvt_tf32(bp[4 * B_STRIDE]);
            }
            #pragma unroll
            for (int mi = 0; mi < 4; mi++)
                #pragma unroll
                for (int ni = 0; ni < 4; ni++)
                    mma_16n8k8(acc[mi][ni], af[mi], bf[ni]);
        }
        __syncthreads();
    }

    // epilogue: per (mi,ni): rows wm+mi*16+grp (+8), cols wn+ni*8+tg*2 (+1)
    #pragma unroll
    for (int mi = 0; mi < 4; mi++) {
        #pragma unroll
        for (int half = 0; half < 2; half++) {
            int row = bm + wm + mi * 16 + grp + half * 8;
            float* orow = Cout + (size_t)row * N + bn;
            const float* rrow = RESID ? (resid + (size_t)row * N + bn) : nullptr;
            #pragma unroll
            for (int ni = 0; ni < 4; ni++) {
                int col = wn + ni * 8 + tg * 2;
                float v0 = acc[mi][ni][half * 2 + 0];
                float v1 = acc[mi][ni][half * 2 + 1];
                if (BIAS) {
                    float2 bb = *(const float2*)(bias + bn + col);
                    v0 += bb.x; v1 += bb.y;
                }
                if (ACT == 1) { v0 = gelu_exact(v0); v1 = gelu_exact(v1); }
                if (RESID) {
                    float2 rr = *(const float2*)(rrow + col);
                    v0 += rr.x; v1 += rr.y;
                }
                *(float2*)(orow + col) = make_float2(v0, v1);
            }
        }
    }
}

// ---------------------------------------------------------------------------
// Attention (fp32 SIMT, full softmax over T=2048, no mask)
// ---------------------------------------------------------------------------
__global__ __launch_bounds__(128) void attn_kernel(
    const float* __restrict__ qkv, float* __restrict__ out)
{
    int qt = blockIdx.x;
    int h  = blockIdx.y;
    int b  = blockIdx.z;
    int t  = threadIdx.x;
    int q_token = b * T + qt * 128 + t;

    const float* qptr = qkv + (size_t)q_token * C3 + h * D;
    float q[D];
    #pragma unroll
    for (int d = 0; d < D; d += 4) {
        float4 v = *(const float4*)(qptr + d);
        q[d]   = v.x * 0.125f;
        q[d+1] = v.y * 0.125f;
        q[d+2] = v.z * 0.125f;
        q[d+3] = v.w * 0.125f;
    }

    float m = -1e30f, l = 0.f;
    float acc[D];
    #pragma unroll
    for (int d = 0; d < D; d++) acc[d] = 0.f;

    __shared__ float Ksh[32][D];
    __shared__ float Vsh[32][D];

    for (int kt = 0; kt < T; kt += 32) {
        #pragma unroll
        for (int i = t; i < 512; i += 128) {
            int r  = i >> 4;
            int d4 = (i & 15) << 2;
            int tok = b * T + kt + r;
            const float* kp = qkv + (size_t)tok * C3 + C + h * D + d4;
            *(float4*)&Ksh[r][d4] = *(const float4*)kp;
            *(float4*)&Vsh[r][d4] = *(const float4*)(kp + C);
        }
        __syncthreads();

        float s[32];
        #pragma unroll
        for (int k = 0; k < 32; k++) {
            float sv = 0.f;
            #pragma unroll
            for (int d = 0; d < D; d += 4) {
                float4 kv = *(const float4*)&Ksh[k][d];
                sv += q[d] * kv.x + q[d+1] * kv.y + q[d+2] * kv.z + q[d+3] * kv.w;
            }
            s[k] = sv;
        }

        float mt = m;
        #pragma unroll
        for (int k = 0; k < 32; k++) mt = fmaxf(mt, s[k]);
        float corr = __expf(m - mt);
        m = mt;
        l *= corr;
        #pragma unroll
        for (int d = 0; d < D; d++) acc[d] *= corr;

        #pragma unroll
        for (int k = 0; k < 32; k++) {
            float p = __expf(s[k] - m);
            l += p;
            #pragma unroll
            for (int d = 0; d < D; d += 4) {
                float4 vv = *(const float4*)&Vsh[k][d];
                acc[d]   += p * vv.x;
                acc[d+1] += p * vv.y;
                acc[d+2] += p * vv.z;
                acc[d+3] += p * vv.w;
            }
        }
        __syncthreads();
    }

    float inv = 1.0f / l;
    float* op = out + (size_t)q_token * C + h * D;
    #pragma unroll
    for (int d = 0; d < D; d += 4) {
        float4 v = make_float4(acc[d] * inv, acc[d+1] * inv, acc[d+2] * inv, acc[d+3] * inv);
        *(float4*)(op + d) = v;
    }
}

// ---------------------------------------------------------------------------
// Launch
// ---------------------------------------------------------------------------
extern "C" void kernel_launch(void* const* d_in, const int* in_sizes, int n_in,
                              void* d_out, int out_size)
{
    const float* x      = (const float*)d_in[0];
    const float* ln1_g  = (const float*)d_in[1];
    const float* ln1_b  = (const float*)d_in[2];
    const float* ln2_g  = (const float*)d_in[3];
    const float* ln2_b  = (const float*)d_in[4];
    const float* w_qkv  = (const float*)d_in[5];
    const float* w_proj = (const float*)d_in[6];
    const float* w1     = (const float*)d_in[7];
    const float* b1     = (const float*)d_in[8];
    const float* w2     = (const float*)d_in[9];
    const float* b2     = (const float*)d_in[10];
    float* out = (float*)d_out;

    float* ln   = nullptr;  cudaGetSymbolAddress((void**)&ln,   g_ln);
    float* qkv  = nullptr;  cudaGetSymbolAddress((void**)&qkv,  g_qkv);
    float* attn = nullptr;  cudaGetSymbolAddress((void**)&attn, g_attn);
    float* h1   = nullptr;  cudaGetSymbolAddress((void**)&h1,   g_h1);

    cudaFuncSetAttribute(gemm_mma<0, false, false>, cudaFuncAttributeMaxDynamicSharedMemorySize, GEMM_SMEM_BYTES);
    cudaFuncSetAttribute(gemm_mma<0, false, true >, cudaFuncAttributeMaxDynamicSharedMemorySize, GEMM_SMEM_BYTES);
    cudaFuncSetAttribute(gemm_mma<1, true,  false>, cudaFuncAttributeMaxDynamicSharedMemorySize, GEMM_SMEM_BYTES);
    cudaFuncSetAttribute(gemm_mma<0, true,  true >, cudaFuncAttributeMaxDynamicSharedMemorySize, GEMM_SMEM_BYTES);

    // 1) LN1(x) -> ln
    ln_kernel<<<BT, 256>>>(x, ln1_g, ln1_b, ln);

    // 2) qkv = ln @ w_qkv
    gemm_mma<0, false, false><<<dim3(C3 / 128, BT / 128), 256, GEMM_SMEM_BYTES>>>(
        ln, w_qkv, nullptr, nullptr, qkv, BT, C3, C);

    // 3) attention
    attn_kernel<<<dim3(T / 128, H, 4), 128>>>(qkv, attn);

    // 4) out = x + attn @ w_proj
    gemm_mma<0, false, true><<<dim3(C / 128, BT / 128), 256, GEMM_SMEM_BYTES>>>(
        attn, w_proj, nullptr, x, out, BT, C, C);

    // 5) LN2(out) -> ln
    ln_kernel<<<BT, 256>>>(out, ln2_g, ln2_b, ln);

    // 6) h1 = gelu(ln @ w1 + b1)
    gemm_mma<1, true, false><<<dim3(DFF / 128, BT / 128), 256, GEMM_SMEM_BYTES>>>(
        ln, w1, b1, nullptr, h1, BT, DFF, C);

    // 7) out = out + h1 @ w2 + b2
    gemm_mma<0, true, true><<<dim3(C / 128, BT / 128), 256, GEMM_SMEM_BYTES>>>(
        h1, w2, b2, out, out, BT, C, DFF);
}

// round 4
// speedup vs baseline: 2.8032x; 1.6209x over previous
#include <cuda_runtime.h>
#include <math.h>
#include <stdint.h>

// ---------------------------------------------------------------------------
// TransformerBlock: mma.sync tf32 GEMMs + mma.sync tf32 flash attention
// Shapes: B=4, T=2048 (BT=8192), C=1024, H=16, D=64, DFF=4096
// ---------------------------------------------------------------------------

#define BT   8192
#define C    1024
#define C3   3072
#define H    16
#define D    64
#define DFF  4096
#define T    2048
#define EPS  1e-5f

// Scratch (__device__ globals; no allocations allowed)
__device__ float g_ln[BT * C];
__device__ float g_qkv[BT * C3];
__device__ float g_attn[BT * C];
__device__ float g_h1[BT * DFF];

// ---------------------------------------------------------------------------
// Helpers
// ---------------------------------------------------------------------------
__device__ __forceinline__ uint32_t smem_u32(const void* p) {
    uint32_t a;
    asm("{ .reg .u64 t; cvta.to.shared.u64 t, %1; cvt.u32.u64 %0, t; }" : "=r"(a) : "l"(p));
    return a;
}
__device__ __forceinline__ void cp_async16(uint32_t dst, const void* src) {
    asm volatile("cp.async.ca.shared.global [%0], [%1], 16;" :: "r"(dst), "l"(src) : "memory");
}
__device__ __forceinline__ void cp_commit() {
    asm volatile("cp.async.commit_group;" ::: "memory");
}
template<int N>
__device__ __forceinline__ void cp_wait() {
    asm volatile("cp.async.wait_group %0;" :: "n"(N) : "memory");
}
__device__ __forceinline__ uint32_t cvt_tf32(float x) {
    uint32_t u;
    asm("cvt.rna.tf32.f32 %0, %1;" : "=r"(u) : "f"(x));
    return u;
}
__device__ __forceinline__ float cvtf_tf32(float x) {
    return __uint_as_float(cvt_tf32(x));
}
__device__ __forceinline__ void mma_16n8k8(float* d, const uint32_t* a, const uint32_t* b) {
    asm volatile(
        "mma.sync.aligned.m16n8k8.row.col.f32.tf32.tf32.f32 "
        "{%0,%1,%2,%3}, {%4,%5,%6,%7}, {%8,%9}, {%0,%1,%2,%3};"
        : "+f"(d[0]), "+f"(d[1]), "+f"(d[2]), "+f"(d[3])
        : "r"(a[0]), "r"(a[1]), "r"(a[2]), "r"(a[3]), "r"(b[0]), "r"(b[1]));
}
__device__ __forceinline__ float gelu_exact(float v) {
    return 0.5f * v * (1.0f + erff(v * 0.70710678118654752f));
}

// ---------------------------------------------------------------------------
// LayerNorm
// ---------------------------------------------------------------------------
__global__ __launch_bounds__(256) void ln_kernel(
    const float* __restrict__ x, const float* __restrict__ g,
    const float* __restrict__ beta, float* __restrict__ out)
{
    int row = blockIdx.x;
    int t = threadIdx.x;
    const float* xr = x + (size_t)row * C;
    float4 xv = *(const float4*)(xr + t * 4);
    float s  = xv.x + xv.y + xv.z + xv.w;
    float s2 = xv.x * xv.x + xv.y * xv.y + xv.z * xv.z + xv.w * xv.w;
    #pragma unroll
    for (int o = 16; o > 0; o >>= 1) {
        s  += __shfl_xor_sync(0xffffffffu, s,  o);
        s2 += __shfl_xor_sync(0xffffffffu, s2, o);
    }
    __shared__ float ss[8], ss2[8];
    int w = t >> 5, lane = t & 31;
    if (lane == 0) { ss[w] = s; ss2[w] = s2; }
    __syncthreads();
    if (w == 0) {
        s  = (lane < 8) ? ss[lane]  : 0.f;
        s2 = (lane < 8) ? ss2[lane] : 0.f;
        #pragma unroll
        for (int o = 4; o > 0; o >>= 1) {
            s  += __shfl_xor_sync(0xffffffffu, s,  o);
            s2 += __shfl_xor_sync(0xffffffffu, s2, o);
        }
        if (lane == 0) { ss[0] = s; ss2[0] = s2; }
    }
    __syncthreads();
    float mu  = ss[0] * (1.0f / C);
    float var = ss2[0] * (1.0f / C) - mu * mu;
    float inv = rsqrtf(var + EPS);
    float4 gv = *(const float4*)(g + t * 4);
    float4 bv = *(const float4*)(beta + t * 4);
    float4 ov;
    ov.x = (xv.x - mu) * inv * gv.x + bv.x;
    ov.y = (xv.y - mu) * inv * gv.y + bv.y;
    ov.z = (xv.z - mu) * inv * gv.z + bv.z;
    ov.w = (xv.w - mu) * inv * gv.w + bv.w;
    *(float4*)(out + (size_t)row * C + t * 4) = ov;
}

// ---------------------------------------------------------------------------
// tf32 mma.sync GEMM (unchanged from R3): 128x128 CTA tile, cp.async dbuf
// ---------------------------------------------------------------------------
#define A_STRIDE 36
#define B_STRIDE 132
#define ASZ (128 * A_STRIDE)
#define BSZ (32 * B_STRIDE)
#define GEMM_SMEM_BYTES (2 * (ASZ + BSZ) * 4)

template<int ACT, bool BIAS, bool RESID>
__global__ __launch_bounds__(256, 2) void gemm_mma(
    const float* __restrict__ A, const float* __restrict__ B,
    const float* __restrict__ bias, const float* __restrict__ resid,
    float* __restrict__ Cout, int M, int N, int K)
{
    extern __shared__ float smem[];
    float* As[2] = { smem,             smem + ASZ };
    float* Bs[2] = { smem + 2 * ASZ,   smem + 2 * ASZ + BSZ };

    int t    = threadIdx.x;
    int lane = t & 31;
    int w    = t >> 5;
    int grp  = lane >> 2;
    int tg   = lane & 3;
    int bm = blockIdx.y * 128;
    int bn = blockIdx.x * 128;
    int wm = (w >> 2) * 64;
    int wn = (w & 3) * 32;

    float acc[4][4][4];
    #pragma unroll
    for (int mi = 0; mi < 4; mi++)
        #pragma unroll
        for (int ni = 0; ni < 4; ni++)
            #pragma unroll
            for (int r = 0; r < 4; r++) acc[mi][ni][r] = 0.f;

    const int NCH = K >> 5;

    auto load_chunk = [&](int c) {
        int buf = c & 1;
        uint32_t aBase = smem_u32(As[buf]);
        uint32_t bBase = smem_u32(Bs[buf]);
        int k0 = c << 5;
        #pragma unroll
        for (int it = 0; it < 4; it++) {
            int idx  = t + it * 256;
            int row  = idx >> 3;
            int col4 = (idx & 7) << 2;
            cp_async16(aBase + (uint32_t)(row * A_STRIDE + col4) * 4,
                       A + (size_t)(bm + row) * K + k0 + col4);
        }
        #pragma unroll
        for (int it = 0; it < 4; it++) {
            int idx  = t + it * 256;
            int row  = idx >> 5;
            int col4 = (idx & 31) << 2;
            cp_async16(bBase + (uint32_t)(row * B_STRIDE + col4) * 4,
                       B + (size_t)(k0 + row) * N + bn + col4);
        }
        cp_commit();
    };

    load_chunk(0);

    for (int c = 0; c < NCH; c++) {
        if (c + 1 < NCH) load_chunk(c + 1);
        if (c + 1 < NCH) cp_wait<1>(); else cp_wait<0>();
        __syncthreads();

        int buf = c & 1;
        const float* Asb = As[buf];
        const float* Bsb = Bs[buf];

        #pragma unroll
        for (int ks = 0; ks < 4; ks++) {
            int k = ks << 3;
            uint32_t af[4][4], bf[4][2];
            #pragma unroll
            for (int mi = 0; mi < 4; mi++) {
                const float* ap = Asb + (wm + mi * 16 + grp) * A_STRIDE + k + tg;
                af[mi][0] = cvt_tf32(ap[0]);
                af[mi][1] = cvt_tf32(ap[8 * A_STRIDE]);
                af[mi][2] = cvt_tf32(ap[4]);
                af[mi][3] = cvt_tf32(ap[8 * A_STRIDE + 4]);
            }
            #pragma unroll
            for (int ni = 0; ni < 4; ni++) {
                const float* bp = Bsb + (k + tg) * B_STRIDE + wn + ni * 8 + grp;
                bf[ni][0] = cvt_tf32(bp[0]);
                bf[ni][1] = cvt_tf32(bp[4 * B_STRIDE]);
            }
            #pragma unroll
            for (int mi = 0; mi < 4; mi++)
                #pragma unroll
                for (int ni = 0; ni < 4; ni++)
                    mma_16n8k8(acc[mi][ni], af[mi], bf[ni]);
        }
        __syncthreads();
    }

    #pragma unroll
    for (int mi = 0; mi < 4; mi++) {
        #pragma unroll
        for (int half = 0; half < 2; half++) {
            int row = bm + wm + mi * 16 + grp + half * 8;
            float* orow = Cout + (size_t)row * N + bn;
            const float* rrow = RESID ? (resid + (size_t)row * N + bn) : nullptr;
            #pragma unroll
            for (int ni = 0; ni < 4; ni++) {
                int col = wn + ni * 8 + tg * 2;
                float v0 = acc[mi][ni][half * 2 + 0];
                float v1 = acc[mi][ni][half * 2 + 1];
                if (BIAS) {
                    float2 bb = *(const float2*)(bias + bn + col);
                    v0 += bb.x; v1 += bb.y;
                }
                if (ACT == 1) { v0 = gelu_exact(v0); v1 = gelu_exact(v1); }
                if (RESID) {
                    float2 rr = *(const float2*)(rrow + col);
                    v0 += rr.x; v1 += rr.y;
                }
                *(float2*)(orow + col) = make_float2(v0, v1);
            }
        }
    }
}

// ---------------------------------------------------------------------------
// Flash attention with mma.sync tf32.
// CTA: 128 q-rows (4 warps x 32 rows = 2 m-tiles), key chunks of 64.
// Smem (tf32 bit patterns, row stride 72 floats, per-8 col permutation):
//   Qs[128][72]  : Q * 1/8, cols permuted
//   Ks[64][72]   : K chunk, cols(d) permuted
//   Vt[64][72]   : V^T chunk [d][key], key index permuted
//   Ps[4][32][72]: P per warp, key cols permuted
// Permutation perm(j) = (j&3)*2 + (j>>2) within each 8-group makes every
// mma fragment's (k, k+4) pair adjacent -> LDS.64; stride 72 (=8 mod 32)
// makes fragment loads bank-conflict-free.
// ---------------------------------------------------------------------------
#define ATT_STR 72
#define ATTN_SMEM_BYTES ((128 + 64 + 64 + 128) * ATT_STR * 4)

__global__ __launch_bounds__(128, 2) void attn_mma_kernel(
    const float* __restrict__ qkv, float* __restrict__ out)
{
    extern __shared__ float sm[];
    float* Qs = sm;                           // 128*72
    float* Ks = Qs + 128 * ATT_STR;           // 64*72
    float* Vt = Ks + 64 * ATT_STR;            // 64*72
    float* Ps = Vt + 64 * ATT_STR;            // 4*32*72

    int qt = blockIdx.x, h = blockIdx.y, b = blockIdx.z;
    int t = threadIdx.x, lane = t & 31, w = t >> 5;
    int grp = lane >> 2, tg = lane & 3;

    const size_t tok0 = (size_t)b * T;

    // ---- stage Q (scaled, tf32, permuted cols), 2048 float4 ----
    #pragma unroll
    for (int it = 0; it < 16; it++) {
        int idx = t + it * 128;
        int row = idx >> 4;
        int c4  = (idx & 15) << 2;
        const float* p = qkv + (tok0 + qt * 128 + row) * C3 + h * D + c4;
        float4 v = *(const float4*)p;
        int base = c4 & ~7;
        int off  = (c4 & 4) ? 1 : 0;
        float* qr = Qs + row * ATT_STR + base + off;
        qr[0] = cvtf_tf32(v.x * 0.125f);
        qr[2] = cvtf_tf32(v.y * 0.125f);
        qr[4] = cvtf_tf32(v.z * 0.125f);
        qr[6] = cvtf_tf32(v.w * 0.125f);
    }

    // softmax state
    float m[2][2], l[2][2];
    float oacc[2][8][4];
    #pragma unroll
    for (int mi = 0; mi < 2; mi++) {
        m[mi][0] = m[mi][1] = -1e30f;
        l[mi][0] = l[mi][1] = 0.f;
        #pragma unroll
        for (int nt = 0; nt < 8; nt++)
            #pragma unroll
            for (int r = 0; r < 4; r++) oacc[mi][nt][r] = 0.f;
    }

    // V staging mapping: key = t&63 (lane-major -> conflict-free transposed STS)
    int vkey  = t & 63;
    int vhalf = t >> 6;
    int pckey = (vkey & ~7) | (((vkey & 3) << 1) | ((vkey >> 2) & 1));

    // P write column positions (permuted) for acc cols tg*2, tg*2+1
    int pc0 = (((tg * 2) & 3) << 1) | (((tg * 2) >> 2) & 1);
    int pc1 = (((tg * 2 + 1) & 3) << 1) | (((tg * 2 + 1) >> 2) & 1);

    float* PsW = Ps + w * 32 * ATT_STR;

    for (int kt = 0; kt < T; kt += 64) {
        __syncthreads();   // Q ready (1st iter) / previous chunk compute done

        // ---- stage K chunk: 64 rows x 64, coalesced LDG ----
        #pragma unroll
        for (int it = 0; it < 8; it++) {
            int idx = t + it * 128;
            int row = idx >> 4;
            int c4  = (idx & 15) << 2;
            const float* p = qkv + (tok0 + kt + row) * C3 + C + h * D + c4;
            float4 v = *(const float4*)p;
            int base = c4 & ~7;
            int off  = (c4 & 4) ? 1 : 0;
            float* kr = Ks + row * ATT_STR + base + off;
            kr[0] = cvtf_tf32(v.x);
            kr[2] = cvtf_tf32(v.y);
            kr[4] = cvtf_tf32(v.z);
            kr[6] = cvtf_tf32(v.w);
        }
        // ---- stage V chunk transposed: Vt[d][pc(key)] ----
        {
            const float* vp = qkv + (tok0 + kt + vkey) * C3 + 2 * C + h * D + vhalf * 32;
            #pragma unroll
            for (int j4 = 0; j4 < 8; j4++) {
                float4 v = *(const float4*)(vp + j4 * 4);
                int d = vhalf * 32 + j4 * 4;
                Vt[(d + 0) * ATT_STR + pckey] = cvtf_tf32(v.x);
                Vt[(d + 1) * ATT_STR + pckey] = cvtf_tf32(v.y);
                Vt[(d + 2) * ATT_STR + pckey] = cvtf_tf32(v.z);
                Vt[(d + 3) * ATT_STR + pckey] = cvtf_tf32(v.w);
            }
        }
        __syncthreads();

        // ---- S = Q @ K^T ----
        float sacc[2][8][4];
        #pragma unroll
        for (int mi = 0; mi < 2; mi++)
            #pragma unroll
            for (int nt = 0; nt < 8; nt++)
                #pragma unroll
                for (int r = 0; r < 4; r++) sacc[mi][nt][r] = 0.f;

        #pragma unroll
        for (int ks = 0; ks < 8; ks++) {
            uint32_t a[2][4];
            #pragma unroll
            for (int mi = 0; mi < 2; mi++) {
                const float2 lo = *(const float2*)(Qs + (w * 32 + mi * 16 + grp)     * ATT_STR + ks * 8 + tg * 2);
                const float2 hi = *(const float2*)(Qs + (w * 32 + mi * 16 + grp + 8) * ATT_STR + ks * 8 + tg * 2);
                a[mi][0] = __float_as_uint(lo.x);
                a[mi][1] = __float_as_uint(hi.x);
                a[mi][2] = __float_as_uint(lo.y);
                a[mi][3] = __float_as_uint(hi.y);
            }
            #pragma unroll
            for (int nt = 0; nt < 8; nt++) {
                const float2 bb = *(const float2*)(Ks + (nt * 8 + grp) * ATT_STR + ks * 8 + tg * 2);
                uint32_t bfr[2] = { __float_as_uint(bb.x), __float_as_uint(bb.y) };
                mma_16n8k8(sacc[0][nt], a[0], bfr);
                mma_16n8k8(sacc[1][nt], a[1], bfr);
            }
        }

        // ---- online softmax + P store ----
        #pragma unroll
        for (int mi = 0; mi < 2; mi++) {
            float r0 = -1e30f, r1 = -1e30f;
            #pragma unroll
            for (int nt = 0; nt < 8; nt++) {
                r0 = fmaxf(r0, fmaxf(sacc[mi][nt][0], sacc[mi][nt][1]));
                r1 = fmaxf(r1, fmaxf(sacc[mi][nt][2], sacc[mi][nt][3]));
            }
            r0 = fmaxf(r0, __shfl_xor_sync(0xffffffffu, r0, 1));
            r0 = fmaxf(r0, __shfl_xor_sync(0xffffffffu, r0, 2));
            r1 = fmaxf(r1, __shfl_xor_sync(0xffffffffu, r1, 1));
            r1 = fmaxf(r1, __shfl_xor_sync(0xffffffffu, r1, 2));
            float mn0 = fmaxf(m[mi][0], r0);
            float mn1 = fmaxf(m[mi][1], r1);
            float c0 = __expf(m[mi][0] - mn0);
            float c1 = __expf(m[mi][1] - mn1);
            m[mi][0] = mn0; m[mi][1] = mn1;
            l[mi][0] *= c0; l[mi][1] *= c1;
            #pragma unroll
            for (int nt = 0; nt < 8; nt++) {
                oacc[mi][nt][0] *= c0; oacc[mi][nt][1] *= c0;
                oacc[mi][nt][2] *= c1; oacc[mi][nt][3] *= c1;
            }
            float* plo = PsW + (mi * 16 + grp)     * ATT_STR;
            float* phi = PsW + (mi * 16 + grp + 8) * ATT_STR;
            #pragma unroll
            for (int nt = 0; nt < 8; nt++) {
                float p0 = __expf(sacc[mi][nt][0] - mn0);
                float p1 = __expf(sacc[mi][nt][1] - mn0);
                float p2 = __expf(sacc[mi][nt][2] - mn1);
                float p3 = __expf(sacc[mi][nt][3] - mn1);
                l[mi][0] += p0 + p1;
                l[mi][1] += p2 + p3;
                plo[nt * 8 + pc0] = cvtf_tf32(p0);
                plo[nt * 8 + pc1] = cvtf_tf32(p1);
                phi[nt * 8 + pc0] = cvtf_tf32(p2);
                phi[nt * 8 + pc1] = cvtf_tf32(p3);
            }
        }
        __syncwarp();

        // ---- O += P @ V ----
        #pragma unroll
        for (int ks = 0; ks < 8; ks++) {
            uint32_t a[2][4];
            #pragma unroll
            for (int mi = 0; mi < 2; mi++) {
                const float2 lo = *(const float2*)(PsW + (mi * 16 + grp)     * ATT_STR + ks * 8 + tg * 2);
                const float2 hi = *(const float2*)(PsW + (mi * 16 + grp + 8) * ATT_STR + ks * 8 + tg * 2);
                a[mi][0] = __float_as_uint(lo.x);
                a[mi][1] = __float_as_uint(hi.x);
                a[mi][2] = __float_as_uint(lo.y);
                a[mi][3] = __float_as_uint(hi.y);
            }
            #pragma unroll
            for (int nt = 0; nt < 8; nt++) {
                const float2 bb = *(const float2*)(Vt + (nt * 8 + grp) * ATT_STR + ks * 8 + tg * 2);
                uint32_t bfr[2] = { __float_as_uint(bb.x), __float_as_uint(bb.y) };
                mma_16n8k8(oacc[0][nt], a[0], bfr);
                mma_16n8k8(oacc[1][nt], a[1], bfr);
            }
        }
    }

    // ---- finalize: divide by l, write out ----
    #pragma unroll
    for (int mi = 0; mi < 2; mi++) {
        float l0 = l[mi][0], l1 = l[mi][1];
        l0 += __shfl_xor_sync(0xffffffffu, l0, 1);
        l0 += __shfl_xor_sync(0xffffffffu, l0, 2);
        l1 += __shfl_xor_sync(0xffffffffu, l1, 1);
        l1 += __shfl_xor_sync(0xffffffffu, l1, 2);
        float i0 = 1.f / l0, i1 = 1.f / l1;
        int rlo = qt * 128 + w * 32 + mi * 16 + grp;
        float* olo = out + (tok0 + rlo) * C + h * D;
        float* ohi = out + (tok0 + rlo + 8) * C + h * D;
        #pragma unroll
        for (int nt = 0; nt < 8; nt++) {
            int col = nt * 8 + tg * 2;
            *(float2*)(olo + col) = make_float2(oacc[mi][nt][0] * i0, oacc[mi][nt][1] * i0);
            *(float2*)(ohi + col) = make_float2(oacc[mi][nt][2] * i1, oacc[mi][nt][3] * i1);
        }
    }
}

// ---------------------------------------------------------------------------
// Launch
// ---------------------------------------------------------------------------
extern "C" void kernel_launch(void* const* d_in, const int* in_sizes, int n_in,
                              void* d_out, int out_size)
{
    const float* x      = (const float*)d_in[0];
    const float* ln1_g  = (const float*)d_in[1];
    const float* ln1_b  = (const float*)d_in[2];
    const float* ln2_g  = (const float*)d_in[3];
    const float* ln2_b  = (const float*)d_in[4];
    const float* w_qkv  = (const float*)d_in[5];
    const float* w_proj = (const float*)d_in[6];
    const float* w1     = (const float*)d_in[7];
    const float* b1     = (const float*)d_in[8];
    const float* w2     = (const float*)d_in[9];
    const float* b2     = (const float*)d_in[10];
    float* out = (float*)d_out;

    float* ln   = nullptr;  cudaGetSymbolAddress((void**)&ln,   g_ln);
    float* qkv  = nullptr;  cudaGetSymbolAddress((void**)&qkv,  g_qkv);
    float* attn = nullptr;  cudaGetSymbolAddress((void**)&attn, g_attn);
    float* h1   = nullptr;  cudaGetSymbolAddress((void**)&h1,   g_h1);

    cudaFuncSetAttribute(gemm_mma<0, false, false>, cudaFuncAttributeMaxDynamicSharedMemorySize, GEMM_SMEM_BYTES);
    cudaFuncSetAttribute(gemm_mma<0, false, true >, cudaFuncAttributeMaxDynamicSharedMemorySize, GEMM_SMEM_BYTES);
    cudaFuncSetAttribute(gemm_mma<1, true,  false>, cudaFuncAttributeMaxDynamicSharedMemorySize, GEMM_SMEM_BYTES);
    cudaFuncSetAttribute(gemm_mma<0, true,  true >, cudaFuncAttributeMaxDynamicSharedMemorySize, GEMM_SMEM_BYTES);
    cudaFuncSetAttribute(attn_mma_kernel, cudaFuncAttributeMaxDynamicSharedMemorySize, ATTN_SMEM_BYTES);

    // 1) LN1(x) -> ln
    ln_kernel<<<BT, 256>>>(x, ln1_g, ln1_b, ln);

    // 2) qkv = ln @ w_qkv
    gemm_mma<0, false, false><<<dim3(C3 / 128, BT / 128), 256, GEMM_SMEM_BYTES>>>(
        ln, w_qkv, nullptr, nullptr, qkv, BT, C3, C);

    // 3) attention (tensor cores)
    attn_mma_kernel<<<dim3(T / 128, H, 4), 128, ATTN_SMEM_BYTES>>>(qkv, attn);

    // 4) out = x + attn @ w_proj
    gemm_mma<0, false, true><<<dim3(C / 128, BT / 128), 256, GEMM_SMEM_BYTES>>>(
        attn, w_proj, nullptr, x, out, BT, C, C);

    // 5) LN2(out) -> ln
    ln_kernel<<<BT, 256>>>(out, ln2_g, ln2_b, ln);

    // 6) h1 = gelu(ln @ w1 + b1)
    gemm_mma<1, true, false><<<dim3(DFF / 128, BT / 128), 256, GEMM_SMEM_BYTES>>>(
        ln, w1, b1, nullptr, h1, BT, DFF, C);

    // 7) out = out + h1 @ w2 + b2
    gemm_mma<0, true, true><<<dim3(C / 128, BT / 128), 256, GEMM_SMEM_BYTES>>>(
        h1, w2, b2, out, out, BT, C, DFF);
}

// round 5
// speedup vs baseline: 3.0808x; 1.0990x over previous
#include <cuda_runtime.h>
#include <math.h>
#include <stdint.h>

// ---------------------------------------------------------------------------
// TransformerBlock: mma.sync tf32 GEMMs (pre-rounded operands) + tf32 flash attn
// Shapes: B=4, T=2048 (BT=8192), C=1024, H=16, D=64, DFF=4096
// ---------------------------------------------------------------------------

#define BT   8192
#define C    1024
#define C3   3072
#define H    16
#define D    64
#define DFF  4096
#define T    2048
#define EPS  1e-5f

// Scratch (__device__ globals; no allocations allowed)
__device__ float g_ln[BT * C];
__device__ float g_qkv[BT * C3];
__device__ float g_attn[BT * C];
__device__ float g_h1[BT * DFF];
// tf32-rounded weight copies
#define WT_QKV  0
#define WT_PROJ (WT_QKV + C * C3)
#define WT_W1   (WT_PROJ + C * C)
#define WT_W2   (WT_W1 + C * DFF)
#define WT_TOT  (WT_W2 + DFF * C)
__device__ float g_wt[WT_TOT];

// ---------------------------------------------------------------------------
// Helpers
// ---------------------------------------------------------------------------
__device__ __forceinline__ uint32_t smem_u32(const void* p) {
    uint32_t a;
    asm("{ .reg .u64 t; cvta.to.shared.u64 t, %1; cvt.u32.u64 %0, t; }" : "=r"(a) : "l"(p));
    return a;
}
__device__ __forceinline__ void cp_async16(uint32_t dst, const void* src) {
    asm volatile("cp.async.ca.shared.global [%0], [%1], 16;" :: "r"(dst), "l"(src) : "memory");
}
__device__ __forceinline__ void cp_commit() {
    asm volatile("cp.async.commit_group;" ::: "memory");
}
template<int N>
__device__ __forceinline__ void cp_wait() {
    asm volatile("cp.async.wait_group %0;" :: "n"(N) : "memory");
}
__device__ __forceinline__ uint32_t cvt_tf32(float x) {
    uint32_t u;
    asm("cvt.rna.tf32.f32 %0, %1;" : "=r"(u) : "f"(x));
    return u;
}
__device__ __forceinline__ float cvtf_tf32(float x) {
    return __uint_as_float(cvt_tf32(x));
}
__device__ __forceinline__ void mma_16n8k8(float* d, const uint32_t* a, const uint32_t* b) {
    asm volatile(
        "mma.sync.aligned.m16n8k8.row.col.f32.tf32.tf32.f32 "
        "{%0,%1,%2,%3}, {%4,%5,%6,%7}, {%8,%9}, {%0,%1,%2,%3};"
        : "+f"(d[0]), "+f"(d[1]), "+f"(d[2]), "+f"(d[3])
        : "r"(a[0]), "r"(a[1]), "r"(a[2]), "r"(a[3]), "r"(b[0]), "r"(b[1]));
}
__device__ __forceinline__ float gelu_exact(float v) {
    return 0.5f * v * (1.0f + erff(v * 0.70710678118654752f));
}

// ---------------------------------------------------------------------------
// Weight convert: elementwise tf32 round (one pass per launch; feeds GEMMs)
// ---------------------------------------------------------------------------
__global__ __launch_bounds__(256) void wcvt_kernel(
    const float* __restrict__ src, float* __restrict__ dst, int n4)
{
    int i = blockIdx.x * 256 + threadIdx.x;
    int stride = gridDim.x * 256;
    for (; i < n4; i += stride) {
        float4 v = *(const float4*)(src + i * 4);
        v.x = cvtf_tf32(v.x); v.y = cvtf_tf32(v.y);
        v.z = cvtf_tf32(v.z); v.w = cvtf_tf32(v.w);
        *(float4*)(dst + i * 4) = v;
    }
}

// ---------------------------------------------------------------------------
// LayerNorm (output tf32-rounded; sole consumer is a GEMM)
// ---------------------------------------------------------------------------
__global__ __launch_bounds__(256) void ln_kernel(
    const float* __restrict__ x, const float* __restrict__ g,
    const float* __restrict__ beta, float* __restrict__ out)
{
    int row = blockIdx.x;
    int t = threadIdx.x;
    const float* xr = x + (size_t)row * C;
    float4 xv = *(const float4*)(xr + t * 4);
    float s  = xv.x + xv.y + xv.z + xv.w;
    float s2 = xv.x * xv.x + xv.y * xv.y + xv.z * xv.z + xv.w * xv.w;
    #pragma unroll
    for (int o = 16; o > 0; o >>= 1) {
        s  += __shfl_xor_sync(0xffffffffu, s,  o);
        s2 += __shfl_xor_sync(0xffffffffu, s2, o);
    }
    __shared__ float ss[8], ss2[8];
    int w = t >> 5, lane = t & 31;
    if (lane == 0) { ss[w] = s; ss2[w] = s2; }
    __syncthreads();
    if (w == 0) {
        s  = (lane < 8) ? ss[lane]  : 0.f;
        s2 = (lane < 8) ? ss2[lane] : 0.f;
        #pragma unroll
        for (int o = 4; o > 0; o >>= 1) {
            s  += __shfl_xor_sync(0xffffffffu, s,  o);
            s2 += __shfl_xor_sync(0xffffffffu, s2, o);
        }
        if (lane == 0) { ss[0] = s; ss2[0] = s2; }
    }
    __syncthreads();
    float mu  = ss[0] * (1.0f / C);
    float var = ss2[0] * (1.0f / C) - mu * mu;
    float inv = rsqrtf(var + EPS);
    float4 gv = *(const float4*)(g + t * 4);
    float4 bv = *(const float4*)(beta + t * 4);
    float4 ov;
    ov.x = cvtf_tf32((xv.x - mu) * inv * gv.x + bv.x);
    ov.y = cvtf_tf32((xv.y - mu) * inv * gv.y + bv.y);
    ov.z = cvtf_tf32((xv.z - mu) * inv * gv.z + bv.z);
    ov.w = cvtf_tf32((xv.w - mu) * inv * gv.w + bv.w);
    *(float4*)(out + (size_t)row * C + t * 4) = ov;
}

// ---------------------------------------------------------------------------
// tf32 mma.sync GEMM: operands PRE-ROUNDED to tf32 -> no cvt in inner loop.
// ROUND_OUT: round result to tf32 (when output feeds another GEMM / attn).
// ---------------------------------------------------------------------------
#define A_STRIDE 36
#define B_STRIDE 132
#define ASZ (128 * A_STRIDE)
#define BSZ (32 * B_STRIDE)
#define GEMM_SMEM_BYTES (2 * (ASZ + BSZ) * 4)

template<int ACT, bool BIAS, bool RESID, bool ROUND_OUT>
__global__ __launch_bounds__(256, 2) void gemm_mma(
    const float* __restrict__ A, const float* __restrict__ B,
    const float* __restrict__ bias, const float* __restrict__ resid,
    float* __restrict__ Cout, int M, int N, int K)
{
    extern __shared__ float smem[];
    float* As[2] = { smem,             smem + ASZ };
    float* Bs[2] = { smem + 2 * ASZ,   smem + 2 * ASZ + BSZ };

    int t    = threadIdx.x;
    int lane = t & 31;
    int w    = t >> 5;
    int grp  = lane >> 2;
    int tg   = lane & 3;
    int bm = blockIdx.y * 128;
    int bn = blockIdx.x * 128;
    int wm = (w >> 2) * 64;
    int wn = (w & 3) * 32;

    float acc[4][4][4];
    #pragma unroll
    for (int mi = 0; mi < 4; mi++)
        #pragma unroll
        for (int ni = 0; ni < 4; ni++)
            #pragma unroll
            for (int r = 0; r < 4; r++) acc[mi][ni][r] = 0.f;

    const int NCH = K >> 5;

    auto load_chunk = [&](int c) {
        int buf = c & 1;
        uint32_t aBase = smem_u32(As[buf]);
        uint32_t bBase = smem_u32(Bs[buf]);
        int k0 = c << 5;
        #pragma unroll
        for (int it = 0; it < 4; it++) {
            int idx  = t + it * 256;
            int row  = idx >> 3;
            int col4 = (idx & 7) << 2;
            cp_async16(aBase + (uint32_t)(row * A_STRIDE + col4) * 4,
                       A + (size_t)(bm + row) * K + k0 + col4);
        }
        #pragma unroll
        for (int it = 0; it < 4; it++) {
            int idx  = t + it * 256;
            int row  = idx >> 5;
            int col4 = (idx & 31) << 2;
            cp_async16(bBase + (uint32_t)(row * B_STRIDE + col4) * 4,
                       B + (size_t)(k0 + row) * N + bn + col4);
        }
        cp_commit();
    };

    load_chunk(0);

    for (int c = 0; c < NCH; c++) {
        if (c + 1 < NCH) load_chunk(c + 1);
        if (c + 1 < NCH) cp_wait<1>(); else cp_wait<0>();
        __syncthreads();

        int buf = c & 1;
        const float* Asb = As[buf];
        const float* Bsb = Bs[buf];

        #pragma unroll
        for (int ks = 0; ks < 4; ks++) {
            int k = ks << 3;
            uint32_t af[4][4], bf[4][2];
            #pragma unroll
            for (int mi = 0; mi < 4; mi++) {
                const float* ap = Asb + (wm + mi * 16 + grp) * A_STRIDE + k + tg;
                af[mi][0] = __float_as_uint(ap[0]);
                af[mi][1] = __float_as_uint(ap[8 * A_STRIDE]);
                af[mi][2] = __float_as_uint(ap[4]);
                af[mi][3] = __float_as_uint(ap[8 * A_STRIDE + 4]);
            }
            #pragma unroll
            for (int ni = 0; ni < 4; ni++) {
                const float* bp = Bsb + (k + tg) * B_STRIDE + wn + ni * 8 + grp;
                bf[ni][0] = __float_as_uint(bp[0]);
                bf[ni][1] = __float_as_uint(bp[4 * B_STRIDE]);
            }
            #pragma unroll
            for (int mi = 0; mi < 4; mi++)
                #pragma unroll
                for (int ni = 0; ni < 4; ni++)
                    mma_16n8k8(acc[mi][ni], af[mi], bf[ni]);
        }
        __syncthreads();
    }

    #pragma unroll
    for (int mi = 0; mi < 4; mi++) {
        #pragma unroll
        for (int half = 0; half < 2; half++) {
            int row = bm + wm + mi * 16 + grp + half * 8;
            float* orow = Cout + (size_t)row * N + bn;
            const float* rrow = RESID ? (resid + (size_t)row * N + bn) : nullptr;
            #pragma unroll
            for (int ni = 0; ni < 4; ni++) {
                int col = wn + ni * 8 + tg * 2;
                float v0 = acc[mi][ni][half * 2 + 0];
                float v1 = acc[mi][ni][half * 2 + 1];
                if (BIAS) {
                    float2 bb = *(const float2*)(bias + bn + col);
                    v0 += bb.x; v1 += bb.y;
                }
                if (ACT == 1) { v0 = gelu_exact(v0); v1 = gelu_exact(v1); }
                if (RESID) {
                    float2 rr = *(const float2*)(rrow + col);
                    v0 += rr.x; v1 += rr.y;
                }
                if (ROUND_OUT) { v0 = cvtf_tf32(v0); v1 = cvtf_tf32(v1); }
                *(float2*)(orow + col) = make_float2(v0, v1);
            }
        }
    }
}

// ---------------------------------------------------------------------------
// Flash attention, mma.sync tf32. qkv is pre-rounded tf32 -> staging copies raw
// (Q scale 0.125 is an exact exponent shift). P rounded before PV MMA.
// Output rounded (feeds proj GEMM).
// ---------------------------------------------------------------------------
#define ATT_STR 72
#define ATTN_SMEM_BYTES ((128 + 64 + 64 + 128) * ATT_STR * 4)

__global__ __launch_bounds__(128, 2) void attn_mma_kernel(
    const float* __restrict__ qkv, float* __restrict__ out)
{
    extern __shared__ float sm[];
    float* Qs = sm;
    float* Ks = Qs + 128 * ATT_STR;
    float* Vt = Ks + 64 * ATT_STR;
    float* Ps = Vt + 64 * ATT_STR;

    int qt = blockIdx.x, h = blockIdx.y, b = blockIdx.z;
    int t = threadIdx.x, lane = t & 31, w = t >> 5;
    int grp = lane >> 2, tg = lane & 3;

    const size_t tok0 = (size_t)b * T;

    #pragma unroll
    for (int it = 0; it < 16; it++) {
        int idx = t + it * 128;
        int row = idx >> 4;
        int c4  = (idx & 15) << 2;
        const float* p = qkv + (tok0 + qt * 128 + row) * C3 + h * D + c4;
        float4 v = *(const float4*)p;
        int base = c4 & ~7;
        int off  = (c4 & 4) ? 1 : 0;
        float* qr = Qs + row * ATT_STR + base + off;
        qr[0] = v.x * 0.125f;
        qr[2] = v.y * 0.125f;
        qr[4] = v.z * 0.125f;
        qr[6] = v.w * 0.125f;
    }

    float m[2][2], l[2][2];
    float oacc[2][8][4];
    #pragma unroll
    for (int mi = 0; mi < 2; mi++) {
        m[mi][0] = m[mi][1] = -1e30f;
        l[mi][0] = l[mi][1] = 0.f;
        #pragma unroll
        for (int nt = 0; nt < 8; nt++)
            #pragma unroll
            for (int r = 0; r < 4; r++) oacc[mi][nt][r] = 0.f;
    }

    int vkey  = t & 63;
    int vhalf = t >> 6;
    int pckey = (vkey & ~7) | (((vkey & 3) << 1) | ((vkey >> 2) & 1));
    int pc0 = (((tg * 2) & 3) << 1) | (((tg * 2) >> 2) & 1);
    int pc1 = (((tg * 2 + 1) & 3) << 1) | (((tg * 2 + 1) >> 2) & 1);

    float* PsW = Ps + w * 32 * ATT_STR;

    for (int kt = 0; kt < T; kt += 64) {
        __syncthreads();

        #pragma unroll
        for (int it = 0; it < 8; it++) {
            int idx = t + it * 128;
            int row = idx >> 4;
            int c4  = (idx & 15) << 2;
            const float* p = qkv + (tok0 + kt + row) * C3 + C + h * D + c4;
            float4 v = *(const float4*)p;
            int base = c4 & ~7;
            int off  = (c4 & 4) ? 1 : 0;
            float* kr = Ks + row * ATT_STR + base + off;
            kr[0] = v.x;
            kr[2] = v.y;
            kr[4] = v.z;
            kr[6] = v.w;
        }
        {
            const float* vp = qkv + (tok0 + kt + vkey) * C3 + 2 * C + h * D + vhalf * 32;
            #pragma unroll
            for (int j4 = 0; j4 < 8; j4++) {
                float4 v = *(const float4*)(vp + j4 * 4);
                int d = vhalf * 32 + j4 * 4;
                Vt[(d + 0) * ATT_STR + pckey] = v.x;
                Vt[(d + 1) * ATT_STR + pckey] = v.y;
                Vt[(d + 2) * ATT_STR + pckey] = v.z;
                Vt[(d + 3) * ATT_STR + pckey] = v.w;
            }
        }
        __syncthreads();

        float sacc[2][8][4];
        #pragma unroll
        for (int mi = 0; mi < 2; mi++)
            #pragma unroll
            for (int nt = 0; nt < 8; nt++)
                #pragma unroll
                for (int r = 0; r < 4; r++) sacc[mi][nt][r] = 0.f;

        #pragma unroll
        for (int ks = 0; ks < 8; ks++) {
            uint32_t a[2][4];
            #pragma unroll
            for (int mi = 0; mi < 2; mi++) {
                const float2 lo = *(const float2*)(Qs + (w * 32 + mi * 16 + grp)     * ATT_STR + ks * 8 + tg * 2);
                const float2 hi = *(const float2*)(Qs + (w * 32 + mi * 16 + grp + 8) * ATT_STR + ks * 8 + tg * 2);
                a[mi][0] = __float_as_uint(lo.x);
                a[mi][1] = __float_as_uint(hi.x);
                a[mi][2] = __float_as_uint(lo.y);
                a[mi][3] = __float_as_uint(hi.y);
            }
            #pragma unroll
            for (int nt = 0; nt < 8; nt++) {
                const float2 bb = *(const float2*)(Ks + (nt * 8 + grp) * ATT_STR + ks * 8 + tg * 2);
                uint32_t bfr[2] = { __float_as_uint(bb.x), __float_as_uint(bb.y) };
                mma_16n8k8(sacc[0][nt], a[0], bfr);
                mma_16n8k8(sacc[1][nt], a[1], bfr);
            }
        }

        #pragma unroll
        for (int mi = 0; mi < 2; mi++) {
            float r0 = -1e30f, r1 = -1e30f;
            #pragma unroll
            for (int nt = 0; nt < 8; nt++) {
                r0 = fmaxf(r0, fmaxf(sacc[mi][nt][0], sacc[mi][nt][1]));
                r1 = fmaxf(r1, fmaxf(sacc[mi][nt][2], sacc[mi][nt][3]));
            }
            r0 = fmaxf(r0, __shfl_xor_sync(0xffffffffu, r0, 1));
            r0 = fmaxf(r0, __shfl_xor_sync(0xffffffffu, r0, 2));
            r1 = fmaxf(r1, __shfl_xor_sync(0xffffffffu, r1, 1));
            r1 = fmaxf(r1, __shfl_xor_sync(0xffffffffu, r1, 2));
            float mn0 = fmaxf(m[mi][0], r0);
            float mn1 = fmaxf(m[mi][1], r1);
            float c0 = __expf(m[mi][0] - mn0);
            float c1 = __expf(m[mi][1] - mn1);
            m[mi][0] = mn0; m[mi][1] = mn1;
            l[mi][0] *= c0; l[mi][1] *= c1;
            #pragma unroll
            for (int nt = 0; nt < 8; nt++) {
                oacc[mi][nt][0] *= c0; oacc[mi][nt][1] *= c0;
                oacc[mi][nt][2] *= c1; oacc[mi][nt][3] *= c1;
            }
            float* plo = PsW + (mi * 16 + grp)     * ATT_STR;
            float* phi = PsW + (mi * 16 + grp + 8) * ATT_STR;
            #pragma unroll
            for (int nt = 0; nt < 8; nt++) {
                float p0 = __expf(sacc[mi][nt][0] - mn0);
                float p1 = __expf(sacc[mi][nt][1] - mn0);
                float p2 = __expf(sacc[mi][nt][2] - mn1);
                float p3 = __expf(sacc[mi][nt][3] - mn1);
                l[mi][0] += p0 + p1;
                l[mi][1] += p2 + p3;
                plo[nt * 8 + pc0] = cvtf_tf32(p0);
                plo[nt * 8 + pc1] = cvtf_tf32(p1);
                phi[nt * 8 + pc0] = cvtf_tf32(p2);
                phi[nt * 8 + pc1] = cvtf_tf32(p3);
            }
        }
        __syncwarp();

        #pragma unroll
        for (int ks = 0; ks < 8; ks++) {
            uint32_t a[2][4];
            #pragma unroll
            for (int mi = 0; mi < 2; mi++) {
                const float2 lo = *(const float2*)(PsW + (mi * 16 + grp)     * ATT_STR + ks * 8 + tg * 2);
                const float2 hi = *(const float2*)(PsW + (mi * 16 + grp + 8) * ATT_STR + ks * 8 + tg * 2);
                a[mi][0] = __float_as_uint(lo.x);
                a[mi][1] = __float_as_uint(hi.x);
                a[mi][2] = __float_as_uint(lo.y);
                a[mi][3] = __float_as_uint(hi.y);
            }
            #pragma unroll
            for (int nt = 0; nt < 8; nt++) {
                const float2 bb = *(const float2*)(Vt + (nt * 8 + grp) * ATT_STR + ks * 8 + tg * 2);
                uint32_t bfr[2] = { __float_as_uint(bb.x), __float_as_uint(bb.y) };
                mma_16n8k8(oacc[0][nt], a[0], bfr);
                mma_16n8k8(oacc[1][nt], a[1], bfr);
            }
        }
    }

    #pragma unroll
    for (int mi = 0; mi < 2; mi++) {
        float l0 = l[mi][0], l1 = l[mi][1];
        l0 += __shfl_xor_sync(0xffffffffu, l0, 1);
        l0 += __shfl_xor_sync(0xffffffffu, l0, 2);
        l1 += __shfl_xor_sync(0xffffffffu, l1, 1);
        l1 += __shfl_xor_sync(0xffffffffu, l1, 2);
        float i0 = 1.f / l0, i1 = 1.f / l1;
        int rlo = qt * 128 + w * 32 + mi * 16 + grp;
        float* olo = out + (tok0 + rlo) * C + h * D;
        float* ohi = out + (tok0 + rlo + 8) * C + h * D;
        #pragma unroll
        for (int nt = 0; nt < 8; nt++) {
            int col = nt * 8 + tg * 2;
            *(float2*)(olo + col) = make_float2(cvtf_tf32(oacc[mi][nt][0] * i0),
                                                cvtf_tf32(oacc[mi][nt][1] * i0));
            *(float2*)(ohi + col) = make_float2(cvtf_tf32(oacc[mi][nt][2] * i1),
                                                cvtf_tf32(oacc[mi][nt][3] * i1));
        }
    }
}

// ---------------------------------------------------------------------------
// Launch
// ---------------------------------------------------------------------------
extern "C" void kernel_launch(void* const* d_in, const int* in_sizes, int n_in,
                              void* d_out, int out_size)
{
    const float* x      = (const float*)d_in[0];
    const float* ln1_g  = (const float*)d_in[1];
    const float* ln1_b  = (const float*)d_in[2];
    const float* ln2_g  = (const float*)d_in[3];
    const float* ln2_b  = (const float*)d_in[4];
    const float* w_qkv  = (const float*)d_in[5];
    const float* w_proj = (const float*)d_in[6];
    const float* w1     = (const float*)d_in[7];
    const float* b1     = (const float*)d_in[8];
    const float* w2     = (const float*)d_in[9];
    const float* b2     = (const float*)d_in[10];
    float* out = (float*)d_out;

    float* ln   = nullptr;  cudaGetSymbolAddress((void**)&ln,   g_ln);
    float* qkv  = nullptr;  cudaGetSymbolAddress((void**)&qkv,  g_qkv);
    float* attn = nullptr;  cudaGetSymbolAddress((void**)&attn, g_attn);
    float* h1   = nullptr;  cudaGetSymbolAddress((void**)&h1,   g_h1);
    float* wt   = nullptr;  cudaGetSymbolAddress((void**)&wt,   g_wt);

    cudaFuncSetAttribute(gemm_mma<0, false, false, true >, cudaFuncAttributeMaxDynamicSharedMemorySize, GEMM_SMEM_BYTES);
    cudaFuncSetAttribute(gemm_mma<0, false, true,  false>, cudaFuncAttributeMaxDynamicSharedMemorySize, GEMM_SMEM_BYTES);
    cudaFuncSetAttribute(gemm_mma<1, true,  false, true >, cudaFuncAttributeMaxDynamicSharedMemorySize, GEMM_SMEM_BYTES);
    cudaFuncSetAttribute(gemm_mma<0, true,  true,  false>, cudaFuncAttributeMaxDynamicSharedMemorySize, GEMM_SMEM_BYTES);
    cudaFuncSetAttribute(attn_mma_kernel, cudaFuncAttributeMaxDynamicSharedMemorySize, ATTN_SMEM_BYTES);

    // 0) round weights to tf32 into scratch
    wcvt_kernel<<<2048, 256>>>(w_qkv,  wt + WT_QKV,  C * C3  / 4);
    wcvt_kernel<<<1024, 256>>>(w_proj, wt + WT_PROJ, C * C   / 4);
    wcvt_kernel<<<2048, 256>>>(w1,     wt + WT_W1,   C * DFF / 4);
    wcvt_kernel<<<2048, 256>>>(w2,     wt + WT_W2,   DFF * C / 4);

    // 1) LN1(x) -> ln (tf32-rounded)
    ln_kernel<<<BT, 256>>>(x, ln1_g, ln1_b, ln);

    // 2) qkv = ln @ w_qkv (output rounded; feeds attention MMAs)
    gemm_mma<0, false, false, true><<<dim3(C3 / 128, BT / 128), 256, GEMM_SMEM_BYTES>>>(
        ln, wt + WT_QKV, nullptr, nullptr, qkv, BT, C3, C);

    // 3) attention (tensor cores; output rounded)
    attn_mma_kernel<<<dim3(T / 128, H, 4), 128, ATTN_SMEM_BYTES>>>(qkv, attn);

    // 4) out = x + attn @ w_proj (fp32 residual, NOT rounded)
    gemm_mma<0, false, true, false><<<dim3(C / 128, BT / 128), 256, GEMM_SMEM_BYTES>>>(
        attn, wt + WT_PROJ, nullptr, x, out, BT, C, C);

    // 5) LN2(out) -> ln (tf32-rounded)
    ln_kernel<<<BT, 256>>>(out, ln2_g, ln2_b, ln);

    // 6) h1 = gelu(ln @ w1 + b1) (output rounded; feeds final GEMM)
    gemm_mma<1, true, false, true><<<dim3(DFF / 128, BT / 128), 256, GEMM_SMEM_BYTES>>>(
        ln, wt + WT_W1, b1, nullptr, h1, BT, DFF, C);

    // 7) out = out + h1 @ w2 + b2 (fp32, NOT rounded)
    gemm_mma<0, true, true, false><<<dim3(C / 128, BT / 128), 256, GEMM_SMEM_BYTES>>>(
        h1, wt + WT_W2, b2, out, out, BT, C, DFF);
}